// round 10
// baseline (speedup 1.0000x reference)
#include <cuda_runtime.h>
#include <cstdint>
#include <math.h>

// Problem constants
#define BSZ 2
#define LSEQ 2048
#define HID 2048
#define NH 16
#define HD 128
#define MTOT (BSZ * LSEQ)          // 4096
#define SCALE 0.08838834764831845f // 1/sqrt(128)

// ---------------- scratch (no allocations allowed) ----------------
__device__ float g_Q[MTOT * HID];  // 32 MB
__device__ float g_K[MTOT * HD];   // 2 MB
__device__ float g_V[MTOT * HD];   // 2 MB
__device__ float g_O[MTOT * HID];  // 32 MB

// cvt.rna.tf32.f32 writes a .b32 destination -> "=r" constraint.
__device__ __forceinline__ uint32_t tf32r(float x) {
    uint32_t y;
    asm("cvt.rna.tf32.f32 %0, %1;" : "=r"(y) : "f"(x));
    return y;
}

__device__ __forceinline__ void mma_tf32(float* c, const uint32_t* a,
                                         uint32_t b0, uint32_t b1) {
    asm volatile(
        "mma.sync.aligned.m16n8k8.row.col.f32.tf32.tf32.f32 "
        "{%0,%1,%2,%3}, {%4,%5,%6,%7}, {%8,%9}, {%0,%1,%2,%3};\n"
        : "+f"(c[0]), "+f"(c[1]), "+f"(c[2]), "+f"(c[3])
        : "r"(a[0]), "r"(a[1]), "r"(a[2]), "r"(a[3]), "r"(b0), "r"(b1));
}

// ================= mma.sync tf32 GEMM: C[M,N] = A[M,K] @ W[N,K]^T =================
// CTA 128x128, 256 threads (8 warps as 4x2; warp tile 32x64). K chunk 32.
// __launch_bounds__(256, 2): cap regs at 128 so TWO CTAs co-reside (16 warps/SM).
#define TBM 128
#define TBN 128
#define TBK 32
#define GK 2048
#define NCHUNK (GK / TBK)   // 64
#define APAD 36
#define ATILE (TBM * APAD)
#define STAGEF (2 * ATILE)
#define GEMM_SMEM (2 * STAGEF * (int)sizeof(uint32_t))  // 73728 B

__global__ __launch_bounds__(256, 2) void gemm_tc(
    const float* __restrict__ A, const float* __restrict__ W,
    float* __restrict__ C, int ldc)
{
    extern __shared__ uint32_t smw[];
    const int tid = threadIdx.x;
    const int lane = tid & 31;
    const int wid = tid >> 5;
    const int warp_m = (wid & 3) * 32;
    const int warp_n = (wid >> 2) * 64;
    const int gid = lane >> 2;
    const int tig = lane & 3;
    const int bm = blockIdx.y * TBM;
    const int bn = blockIdx.x * TBN;

    const int lrow = tid >> 3;
    const int lc4 = (tid & 7) * 4;

    float acc[2][8][4];
#pragma unroll
    for (int i = 0; i < 2; i++)
#pragma unroll
        for (int j = 0; j < 8; j++)
#pragma unroll
            for (int q = 0; q < 4; q++) acc[i][j][q] = 0.f;

    float4 ra[4], rb[4];

#pragma unroll
    for (int i = 0; i < 4; i++) {
        int row = lrow + i * 32;
        ra[i] = *(const float4*)(A + (size_t)(bm + row) * GK + lc4);
        rb[i] = *(const float4*)(W + (size_t)(bn + row) * GK + lc4);
    }
#pragma unroll
    for (int i = 0; i < 4; i++) {
        int row = lrow + i * 32;
        uint32_t* pa = &smw[row * APAD + lc4];
        uint32_t* pb = &smw[ATILE + row * APAD + lc4];
        pa[0] = tf32r(ra[i].x); pa[1] = tf32r(ra[i].y);
        pa[2] = tf32r(ra[i].z); pa[3] = tf32r(ra[i].w);
        pb[0] = tf32r(rb[i].x); pb[1] = tf32r(rb[i].y);
        pb[2] = tf32r(rb[i].z); pb[3] = tf32r(rb[i].w);
    }
    __syncthreads();

#pragma unroll 1
    for (int c = 0; c < NCHUNK; c++) {
        const int s = c & 1;
        const bool more = (c + 1 < NCHUNK);
        if (more) {
            const int k0 = (c + 1) * TBK;
#pragma unroll
            for (int i = 0; i < 4; i++) {
                int row = lrow + i * 32;
                ra[i] = *(const float4*)(A + (size_t)(bm + row) * GK + k0 + lc4);
                rb[i] = *(const float4*)(W + (size_t)(bn + row) * GK + k0 + lc4);
            }
        }

        const uint32_t* As_ = &smw[s * STAGEF];
        const uint32_t* Ws_ = &smw[s * STAGEF + ATILE];
#pragma unroll
        for (int ks = 0; ks < 4; ks++) {
            const int k = ks * 8;
            uint32_t af[2][4];
#pragma unroll
            for (int i = 0; i < 2; i++) {
                int r0 = warp_m + i * 16 + gid;
                af[i][0] = As_[r0 * APAD + k + tig];
                af[i][1] = As_[(r0 + 8) * APAD + k + tig];
                af[i][2] = As_[r0 * APAD + k + tig + 4];
                af[i][3] = As_[(r0 + 8) * APAD + k + tig + 4];
            }
#pragma unroll
            for (int j = 0; j < 8; j++) {
                int cn = warp_n + j * 8 + gid;
                uint32_t b0 = Ws_[cn * APAD + k + tig];
                uint32_t b1 = Ws_[cn * APAD + k + tig + 4];
                mma_tf32(acc[0][j], af[0], b0, b1);
                mma_tf32(acc[1][j], af[1], b0, b1);
            }
        }

        if (more) {
            uint32_t* Ad = &smw[(s ^ 1) * STAGEF];
            uint32_t* Bd = &smw[(s ^ 1) * STAGEF + ATILE];
#pragma unroll
            for (int i = 0; i < 4; i++) {
                int row = lrow + i * 32;
                uint32_t* pa = &Ad[row * APAD + lc4];
                uint32_t* pb = &Bd[row * APAD + lc4];
                pa[0] = tf32r(ra[i].x); pa[1] = tf32r(ra[i].y);
                pa[2] = tf32r(ra[i].z); pa[3] = tf32r(ra[i].w);
                pb[0] = tf32r(rb[i].x); pb[1] = tf32r(rb[i].y);
                pb[2] = tf32r(rb[i].z); pb[3] = tf32r(rb[i].w);
            }
        }
        __syncthreads();
    }

#pragma unroll
    for (int i = 0; i < 2; i++) {
        int r0 = bm + warp_m + i * 16 + gid;
#pragma unroll
        for (int j = 0; j < 8; j++) {
            int cn = bn + warp_n + j * 8 + 2 * tig;
            *(float2*)(C + (size_t)r0 * ldc + cn) =
                make_float2(acc[i][j][0], acc[i][j][1]);
            *(float2*)(C + (size_t)(r0 + 8) * ldc + cn) =
                make_float2(acc[i][j][2], acc[i][j][3]);
        }
    }
}

// ============== Flash attention v3 (occupancy-first, tf32 mma, causal, MQA) ==============
// CTA: 64 q-rows, FBN=32 kv tiles, 256 threads = 8 warps:
//   rg = (wid&3)*16  -> warp owns q-rows rg..rg+15 (softmax fully warp-local)
//   dh = (wid>>2)*64 -> warp owns d-columns dh..dh+63 for PV/O
// Both d-half warps compute S redundantly (m16 x n32) -> zero cross-warp exchange.
// Small footprint (o[8][4], s[4][4], ~104KB smem, <=128 regs) -> 2 CTAs/SM.
#define FBM 64
#define FBN 32
#define QSTR 132   // stride mod 32 = 4 -> bank = 4*gid + tig (conflict-free)
#define VSTR 36
#define KTILE (FBN * QSTR)   // 4224 words
#define VTILE (HD * VSTR)    // 4608 words
#define FL_QS 0
#define FL_KS (FL_QS + FBM * QSTR)      // Qs: 8448 words
#define FL_VT (FL_KS + 2 * KTILE)       // Ks: 2 x 4224
#define FL_MK (FL_VT + 2 * VTILE)       // Vt: 2 x 4608
#define FLASH_SMEM ((FL_MK + 2 * FBN) * (int)sizeof(uint32_t))  // 104,704 B

__global__ __launch_bounds__(256, 2) void flash_tc(
    const float* __restrict__ Q, const float* __restrict__ K,
    const float* __restrict__ V, const int* __restrict__ mask,
    float* __restrict__ O)
{
    extern __shared__ uint32_t fsw[];
    uint32_t* Qs = fsw + FL_QS;
    uint32_t* Ksb = fsw + FL_KS;
    uint32_t* Vtb = fsw + FL_VT;
    int* mkb = (int*)(fsw + FL_MK);

    const int m0 = (gridDim.x - 1 - blockIdx.x) * FBM;  // heavy tiles first
    const int bh = blockIdx.y;
    const int b = bh / NH;
    const int h = bh % NH;
    const int tid = threadIdx.x;
    const int lane = tid & 31;
    const int wid = tid >> 5;
    const int gid = lane >> 2;
    const int tig = lane & 3;
    const int rg = (wid & 3) * 16;   // row group
    const int dh = (wid >> 2) * 64;  // d half

    // ---- Q tile (64 x 128) -> tf32 smem ----
    for (int f = tid; f < FBM * 32; f += 256) {
        int row = f >> 5, c4 = (f & 31) * 4;
        float4 v = *(const float4*)(Q + (size_t)(b * LSEQ + m0 + row) * HID + h * HD + c4);
        uint4 u = make_uint4(tf32r(v.x), tf32r(v.y), tf32r(v.z), tf32r(v.w));
        *(uint4*)&Qs[row * QSTR + c4] = u;
    }
    // ---- prologue: KV tile 0 into buffer 0 ----
    for (int f = tid; f < FBN * 32; f += 256) {
        int row = f >> 5, c4 = (f & 31) * 4;
        float4 v = *(const float4*)(K + (size_t)(b * LSEQ + row) * HD + c4);
        uint4 u = make_uint4(tf32r(v.x), tf32r(v.y), tf32r(v.z), tf32r(v.w));
        *(uint4*)&Ksb[row * QSTR + c4] = u;
    }
    for (int f = tid; f < FBN * 32; f += 256) {
        int row = f & 31, c4 = (f >> 5) * 4;
        float4 v = *(const float4*)(V + (size_t)(b * LSEQ + row) * HD + c4);
        Vtb[(c4 + 0) * VSTR + row] = tf32r(v.x);
        Vtb[(c4 + 1) * VSTR + row] = tf32r(v.y);
        Vtb[(c4 + 2) * VSTR + row] = tf32r(v.z);
        Vtb[(c4 + 3) * VSTR + row] = tf32r(v.w);
    }
    if (tid < FBN) mkb[tid] = mask[b * LSEQ + tid];
    __syncthreads();

    float o[8][4];
#pragma unroll
    for (int dj = 0; dj < 8; dj++)
#pragma unroll
        for (int c = 0; c < 4; c++) o[dj][c] = 0.f;
    float m_a = -1e30f, m_b = -1e30f, l_a = 0.f, l_b = 0.f;

    const int rA = m0 + rg + gid;
    const int rB = rA + 8;
    const int srcA = (lane & ~3) | (tig >> 1);
    const int srcB = srcA + 2;
    const int ntiles = m0 / FBN + FBM / FBN;  // m0/32 + 2

#pragma unroll 1
    for (int t = 0; t < ntiles; t++) {
        const int buf = t & 1;
        const uint32_t* Ks = Ksb + buf * KTILE;
        const uint32_t* Vt = Vtb + buf * VTILE;
        const int* mk = mkb + buf * FBN;
        const int n0 = t * FBN;
        const bool more = (t + 1 < ntiles);

        // ---- stage next KV tile in registers ----
        float4 ka[4], va[4];
        int mreg = 1;
        if (more) {
            const int nn = n0 + FBN;
#pragma unroll
            for (int i = 0; i < 4; i++) {
                int f = tid + i * 256;
                int row = f >> 5, c4 = (f & 31) * 4;
                ka[i] = *(const float4*)(K + (size_t)(b * LSEQ + nn + row) * HD + c4);
            }
#pragma unroll
            for (int i = 0; i < 4; i++) {
                int f = tid + i * 256;
                int row = f & 31, c4 = (f >> 5) * 4;
                va[i] = *(const float4*)(V + (size_t)(b * LSEQ + nn + row) * HD + c4);
            }
            if (tid < FBN) mreg = mask[b * LSEQ + nn + tid];
        }

        if (n0 <= m0 + rg + 15) {   // per-row-group causal skip
            // ---- S = Q K^T : m16 x n32 (redundant across d-half warps) ----
            float s[4][4];
#pragma unroll
            for (int j = 0; j < 4; j++)
#pragma unroll
                for (int c = 0; c < 4; c++) s[j][c] = 0.f;
#pragma unroll
            for (int k8 = 0; k8 < 16; k8++) {
                const int k = k8 * 8;
                uint32_t a[4];
                a[0] = Qs[(rg + gid) * QSTR + k + tig];
                a[1] = Qs[(rg + gid + 8) * QSTR + k + tig];
                a[2] = Qs[(rg + gid) * QSTR + k + tig + 4];
                a[3] = Qs[(rg + gid + 8) * QSTR + k + tig + 4];
#pragma unroll
                for (int j = 0; j < 4; j++) {
                    uint32_t b0 = Ks[(j * 8 + gid) * QSTR + k + tig];
                    uint32_t b1 = Ks[(j * 8 + gid) * QSTR + k + tig + 4];
                    mma_tf32(s[j], a, b0, b1);
                }
            }

            // ---- scale + causal + pad mask; warp-local row max ----
            float mxA = -1e30f, mxB = -1e30f;
#pragma unroll
            for (int j = 0; j < 4; j++) {
#pragma unroll
                for (int c = 0; c < 4; c++) {
                    int lcol = j * 8 + 2 * tig + (c & 1);
                    int col = n0 + lcol;
                    int r = (c < 2) ? rA : rB;
                    float v = s[j][c] * SCALE;
                    if (col > r || mk[lcol] == 0) v = -1e30f;
                    s[j][c] = v;
                    if (c < 2) mxA = fmaxf(mxA, v); else mxB = fmaxf(mxB, v);
                }
            }
            mxA = fmaxf(mxA, __shfl_xor_sync(0xffffffffu, mxA, 1));
            mxA = fmaxf(mxA, __shfl_xor_sync(0xffffffffu, mxA, 2));
            mxB = fmaxf(mxB, __shfl_xor_sync(0xffffffffu, mxB, 1));
            mxB = fmaxf(mxB, __shfl_xor_sync(0xffffffffu, mxB, 2));
            const float mnA = fmaxf(m_a, mxA), mnB = fmaxf(m_b, mxB);
            const float crA = __expf(m_a - mnA), crB = __expf(m_b - mnB);
            m_a = mnA; m_b = mnB;

            // ---- exp + row sums ----
            float smA = 0.f, smB = 0.f;
#pragma unroll
            for (int j = 0; j < 4; j++) {
#pragma unroll
                for (int c = 0; c < 4; c++) {
                    float p = __expf(s[j][c] - ((c < 2) ? mnA : mnB));
                    s[j][c] = p;
                    if (c < 2) smA += p; else smB += p;
                }
            }
            smA += __shfl_xor_sync(0xffffffffu, smA, 1);
            smA += __shfl_xor_sync(0xffffffffu, smA, 2);
            smB += __shfl_xor_sync(0xffffffffu, smB, 1);
            smB += __shfl_xor_sync(0xffffffffu, smB, 2);
            l_a = l_a * crA + smA;
            l_b = l_b * crB + smB;

            // ---- rescale O, then O += P V (P via intra-quad shuffle transpose) ----
#pragma unroll
            for (int dj = 0; dj < 8; dj++) {
                o[dj][0] *= crA; o[dj][1] *= crA;
                o[dj][2] *= crB; o[dj][3] *= crB;
            }
#pragma unroll
            for (int j = 0; j < 4; j++) {   // j = k8-group of PV (32 keys)
                float v0 = __shfl_sync(0xffffffffu, s[j][0], srcA);
                float v1 = __shfl_sync(0xffffffffu, s[j][1], srcA);
                float v2 = __shfl_sync(0xffffffffu, s[j][2], srcA);
                float v3 = __shfl_sync(0xffffffffu, s[j][3], srcA);
                float w0 = __shfl_sync(0xffffffffu, s[j][0], srcB);
                float w1 = __shfl_sync(0xffffffffu, s[j][1], srcB);
                float w2 = __shfl_sync(0xffffffffu, s[j][2], srcB);
                float w3 = __shfl_sync(0xffffffffu, s[j][3], srcB);
                uint32_t a[4];
                a[0] = tf32r((tig & 1) ? v1 : v0);
                a[1] = tf32r((tig & 1) ? v3 : v2);
                a[2] = tf32r((tig & 1) ? w1 : w0);
                a[3] = tf32r((tig & 1) ? w3 : w2);
                const int k = j * 8;
#pragma unroll
                for (int dj = 0; dj < 8; dj++) {
                    uint32_t b0 = Vt[(dh + dj * 8 + gid) * VSTR + k + tig];
                    uint32_t b1 = Vt[(dh + dj * 8 + gid) * VSTR + k + tig + 4];
                    mma_tf32(o[dj], a, b0, b1);
                }
            }
        }

        // ---- commit staged tile into other buffer ----
        if (more) {
            uint32_t* Kd = Ksb + (buf ^ 1) * KTILE;
            uint32_t* Vd = Vtb + (buf ^ 1) * VTILE;
#pragma unroll
            for (int i = 0; i < 4; i++) {
                int f = tid + i * 256;
                int row = f >> 5, c4 = (f & 31) * 4;
                uint4 u = make_uint4(tf32r(ka[i].x), tf32r(ka[i].y),
                                     tf32r(ka[i].z), tf32r(ka[i].w));
                *(uint4*)&Kd[row * QSTR + c4] = u;
            }
#pragma unroll
            for (int i = 0; i < 4; i++) {
                int f = tid + i * 256;
                int row = f & 31, c4 = (f >> 5) * 4;
                Vd[(c4 + 0) * VSTR + row] = tf32r(va[i].x);
                Vd[(c4 + 1) * VSTR + row] = tf32r(va[i].y);
                Vd[(c4 + 2) * VSTR + row] = tf32r(va[i].z);
                Vd[(c4 + 3) * VSTR + row] = tf32r(va[i].w);
            }
            if (tid < FBN) mkb[(buf ^ 1) * FBN + tid] = mreg;
        }
        __syncthreads();
    }

    // ---- normalize + write (this warp's d-half only) ----
    const float invA = (l_a > 0.f) ? (1.f / l_a) : 0.f;
    const float invB = (l_b > 0.f) ? (1.f / l_b) : 0.f;
    float* rowA = O + (size_t)(b * LSEQ + m0 + rg + gid) * HID + h * HD + dh;
    float* rowB = rowA + (size_t)8 * HID;
#pragma unroll
    for (int dj = 0; dj < 8; dj++) {
        int cb = dj * 8 + 2 * tig;
        *(float2*)(rowA + cb) = make_float2(o[dj][0] * invA, o[dj][1] * invA);
        *(float2*)(rowB + cb) = make_float2(o[dj][2] * invB, o[dj][3] * invB);
    }
}

// ---------------- launch ----------------
extern "C" void kernel_launch(void* const* d_in, const int* in_sizes, int n_in,
                              void* d_out, int out_size)
{
    const float* x   = (const float*)d_in[0];
    const int* mask  = (const int*)d_in[1];
    const float* Wq  = (const float*)d_in[2];
    const float* Wk  = (const float*)d_in[3];
    const float* Wv  = (const float*)d_in[4];
    const float* Wo  = (const float*)d_in[5];
    float* out       = (float*)d_out;

    float *Qp, *Kp, *Vp, *Op;
    cudaGetSymbolAddress((void**)&Qp, g_Q);
    cudaGetSymbolAddress((void**)&Kp, g_K);
    cudaGetSymbolAddress((void**)&Vp, g_V);
    cudaGetSymbolAddress((void**)&Op, g_O);

    cudaFuncSetAttribute(gemm_tc, cudaFuncAttributeMaxDynamicSharedMemorySize, GEMM_SMEM);
    cudaFuncSetAttribute(flash_tc, cudaFuncAttributeMaxDynamicSharedMemorySize, FLASH_SMEM);

    gemm_tc<<<dim3(HID / TBN, MTOT / TBM), 256, GEMM_SMEM>>>(x, Wq, Qp, HID);
    gemm_tc<<<dim3(HD / TBN, MTOT / TBM), 256, GEMM_SMEM>>>(x, Wk, Kp, HD);
    gemm_tc<<<dim3(HD / TBN, MTOT / TBM), 256, GEMM_SMEM>>>(x, Wv, Vp, HD);
    flash_tc<<<dim3(LSEQ / FBM, BSZ * NH), 256, FLASH_SMEM>>>(Qp, Kp, Vp, mask, Op);
    gemm_tc<<<dim3(HID / TBN, MTOT / TBM), 256, GEMM_SMEM>>>(Op, Wo, out, HID);
}

// round 13
// speedup vs baseline: 1.5850x; 1.5850x over previous
#include <cuda_runtime.h>
#include <cuda_fp16.h>
#include <cstdint>
#include <math.h>

// Problem constants
#define BSZ 2
#define LSEQ 2048
#define HID 2048
#define NH 16
#define HD 128
#define MTOT (BSZ * LSEQ)          // 4096
#define SCALE 0.08838834764831845f // 1/sqrt(128)

// ---------------- scratch (no allocations allowed) ----------------
__device__ float g_Q[MTOT * HID];  // 32 MB
__device__ float g_K[MTOT * HD];   // 2 MB
__device__ float g_V[MTOT * HD];   // 2 MB
__device__ float g_O[MTOT * HID];  // 32 MB

__device__ __forceinline__ uint32_t f16x2(float lo, float hi) {
    __half2 h = __floats2half2_rn(lo, hi);
    return *reinterpret_cast<uint32_t*>(&h);
}

// D(f32) += A(f16) * B(f16): m16n8k16
__device__ __forceinline__ void mma_f16(float* c, const uint32_t* a,
                                        uint32_t b0, uint32_t b1) {
    asm volatile(
        "mma.sync.aligned.m16n8k16.row.col.f32.f16.f16.f32 "
        "{%0,%1,%2,%3}, {%4,%5,%6,%7}, {%8,%9}, {%0,%1,%2,%3};\n"
        : "+f"(c[0]), "+f"(c[1]), "+f"(c[2]), "+f"(c[3])
        : "r"(a[0]), "r"(a[1]), "r"(a[2]), "r"(a[3]), "r"(b0), "r"(b1));
}

// ================= fp16 mma GEMM: C[M,N] = A[M,K] @ W[N,K]^T =================
// CTA 128x128, 256 threads (8 warps as 4x2; warp tile 32x64). K chunk 32 (2 k16).
// smem tiles hold fp16 pairs: row = 16 data words (+4 pad); stride 20 = conflict-free
// fragment LDS (bank = (4*gid + tig + const) permutation).
#define TBM 128
#define TBN 128
#define TBK 32
#define GK 2048
#define NCHUNK (GK / TBK)   // 64
#define APAD 20             // words per row (16 data + 4 pad)
#define ATILE (TBM * APAD)  // words per A (or B) tile
#define STAGEF (2 * ATILE)
#define GEMM_SMEM (2 * STAGEF * (int)sizeof(uint32_t))  // 40960 B

__global__ __launch_bounds__(256) void gemm_tc(
    const float* __restrict__ A, const float* __restrict__ W,
    float* __restrict__ C, int ldc)
{
    extern __shared__ uint32_t smw[];
    const int tid = threadIdx.x;
    const int lane = tid & 31;
    const int wid = tid >> 5;
    const int warp_m = (wid & 3) * 32;
    const int warp_n = (wid >> 2) * 64;
    const int gid = lane >> 2;
    const int tig = lane & 3;
    const int bm = blockIdx.y * TBM;
    const int bn = blockIdx.x * TBN;

    const int lrow = tid >> 3;           // 0..31 (+32*i)
    const int lc4 = (tid & 7) * 4;       // f32 col
    const int wcol = (tid & 7) * 2;      // smem word col

    float acc[2][8][4];
#pragma unroll
    for (int i = 0; i < 2; i++)
#pragma unroll
        for (int j = 0; j < 8; j++)
#pragma unroll
            for (int q = 0; q < 4; q++) acc[i][j][q] = 0.f;

    float4 ra[4], rb[4];

    // ---- prefetch chunk 0 ----
#pragma unroll
    for (int i = 0; i < 4; i++) {
        int row = lrow + i * 32;
        ra[i] = *(const float4*)(A + (size_t)(bm + row) * GK + lc4);
        rb[i] = *(const float4*)(W + (size_t)(bn + row) * GK + lc4);
    }
#pragma unroll
    for (int i = 0; i < 4; i++) {
        int row = lrow + i * 32;
        *(uint2*)&smw[row * APAD + wcol] =
            make_uint2(f16x2(ra[i].x, ra[i].y), f16x2(ra[i].z, ra[i].w));
        *(uint2*)&smw[ATILE + row * APAD + wcol] =
            make_uint2(f16x2(rb[i].x, rb[i].y), f16x2(rb[i].z, rb[i].w));
    }
    __syncthreads();

#pragma unroll 1
    for (int c = 0; c < NCHUNK; c++) {
        const int s = c & 1;
        const bool more = (c + 1 < NCHUNK);
        if (more) {
            const int k0 = (c + 1) * TBK;
#pragma unroll
            for (int i = 0; i < 4; i++) {
                int row = lrow + i * 32;
                ra[i] = *(const float4*)(A + (size_t)(bm + row) * GK + k0 + lc4);
                rb[i] = *(const float4*)(W + (size_t)(bn + row) * GK + k0 + lc4);
            }
        }

        const uint32_t* As_ = &smw[s * STAGEF];
        const uint32_t* Ws_ = &smw[s * STAGEF + ATILE];
#pragma unroll
        for (int ks = 0; ks < 2; ks++) {            // 2 x k16
            const int kw = ks * 8;
            uint32_t af[2][4];
#pragma unroll
            for (int i = 0; i < 2; i++) {
                int r0 = warp_m + i * 16 + gid;
                af[i][0] = As_[r0 * APAD + kw + tig];
                af[i][1] = As_[(r0 + 8) * APAD + kw + tig];
                af[i][2] = As_[r0 * APAD + kw + tig + 4];
                af[i][3] = As_[(r0 + 8) * APAD + kw + tig + 4];
            }
#pragma unroll
            for (int j = 0; j < 8; j++) {
                int cn = warp_n + j * 8 + gid;
                uint32_t b0 = Ws_[cn * APAD + kw + tig];
                uint32_t b1 = Ws_[cn * APAD + kw + tig + 4];
                mma_f16(acc[0][j], af[0], b0, b1);
                mma_f16(acc[1][j], af[1], b0, b1);
            }
        }

        if (more) {
            uint32_t* Ad = &smw[(s ^ 1) * STAGEF];
            uint32_t* Bd = &smw[(s ^ 1) * STAGEF + ATILE];
#pragma unroll
            for (int i = 0; i < 4; i++) {
                int row = lrow + i * 32;
                *(uint2*)&Ad[row * APAD + wcol] =
                    make_uint2(f16x2(ra[i].x, ra[i].y), f16x2(ra[i].z, ra[i].w));
                *(uint2*)&Bd[row * APAD + wcol] =
                    make_uint2(f16x2(rb[i].x, rb[i].y), f16x2(rb[i].z, rb[i].w));
            }
        }
        __syncthreads();
    }

    // ---- epilogue (same f32 accumulator layout) ----
#pragma unroll
    for (int i = 0; i < 2; i++) {
        int r0 = bm + warp_m + i * 16 + gid;
#pragma unroll
        for (int j = 0; j < 8; j++) {
            int cn = bn + warp_n + j * 8 + 2 * tig;
            *(float2*)(C + (size_t)r0 * ldc + cn) =
                make_float2(acc[i][j][0], acc[i][j][1]);
            *(float2*)(C + (size_t)(r0 + 8) * ldc + cn) =
                make_float2(acc[i][j][2], acc[i][j][3]);
        }
    }
}

// ============== Flash attention v4 (fp16 mma, warp-owns-rows, causal, MQA) ==============
// v2 structure: CTA 128 q-rows x d=128; 8 warps; warp w owns rows w*16..w*16+15.
// fp16 m16n8k16: S = Q K^T (m16 x n64), softmax warp-local in f32, P packs DIRECTLY
// into the PV A-fragment (accumulator layout == A-fragment layout: zero shuffles).
// K/V smem double-buffered fp16; register-staged loads; one syncthreads per tile.
#define FBM 128
#define FBN 64
#define QSTR 68    // words/row (64 data + 4 pad); stride%32==4 -> conflict-free
#define VSTR 36    // words/row (32 data + 4 pad)
#define KTILE (FBN * QSTR)   // 4352 words
#define VTILE (HD * VSTR)    // 4608 words
#define FL_QS 0
#define FL_KS (FL_QS + FBM * QSTR)      // Qs: 8704 words
#define FL_VT (FL_KS + 2 * KTILE)       // Ks: 2 x 4352
#define FL_MK (FL_VT + 2 * VTILE)       // Vt: 2 x 4608
#define FLASH_SMEM ((FL_MK + 2 * FBN) * (int)sizeof(uint32_t))  // 107,520 B

__global__ __launch_bounds__(256) void flash_tc(
    const float* __restrict__ Q, const float* __restrict__ K,
    const float* __restrict__ V, const int* __restrict__ mask,
    float* __restrict__ O)
{
    extern __shared__ uint32_t fsw[];
    uint32_t* Qs = fsw + FL_QS;
    uint32_t* Ksb = fsw + FL_KS;
    uint32_t* Vtb = fsw + FL_VT;
    int* mkb = (int*)(fsw + FL_MK);

    const int m0 = (gridDim.x - 1 - blockIdx.x) * FBM;  // heavy tiles first
    const int bh = blockIdx.y;
    const int b = bh / NH;
    const int h = bh % NH;
    const int tid = threadIdx.x;
    const int lane = tid & 31;
    const int wid = tid >> 5;
    const int gid = lane >> 2;
    const int tig = lane & 3;
    const int wm = wid * 16;

    // ---- Q tile (128 x 128) -> fp16 smem ----
    for (int f = tid; f < FBM * 32; f += 256) {
        int row = f >> 5, c4 = (f & 31) * 4;
        float4 v = *(const float4*)(Q + (size_t)(b * LSEQ + m0 + row) * HID + h * HD + c4);
        *(uint2*)&Qs[row * QSTR + (f & 31) * 2] =
            make_uint2(f16x2(v.x, v.y), f16x2(v.z, v.w));
    }
    // ---- prologue: KV tile 0 into buffer 0 ----
    for (int f = tid; f < FBN * 32; f += 256) {
        int row = f >> 5, c4 = (f & 31) * 4;
        float4 v = *(const float4*)(K + (size_t)(b * LSEQ + row) * HD + c4);
        *(uint2*)&Ksb[row * QSTR + (f & 31) * 2] =
            make_uint2(f16x2(v.x, v.y), f16x2(v.z, v.w));
    }
    {
        __half* hV = (__half*)Vtb;
        for (int f = tid; f < FBN * 32; f += 256) {
            int row = f & 63, c4 = (f >> 6) * 4;
            float4 v = *(const float4*)(V + (size_t)(b * LSEQ + row) * HD + c4);
            int base = (row >> 1) * 2 + (row & 1);
            hV[(c4 + 0) * (VSTR * 2) + base] = __float2half_rn(v.x);
            hV[(c4 + 1) * (VSTR * 2) + base] = __float2half_rn(v.y);
            hV[(c4 + 2) * (VSTR * 2) + base] = __float2half_rn(v.z);
            hV[(c4 + 3) * (VSTR * 2) + base] = __float2half_rn(v.w);
        }
    }
    if (tid < FBN) mkb[tid] = mask[b * LSEQ + tid];
    __syncthreads();

    float o[16][4];
#pragma unroll
    for (int dj = 0; dj < 16; dj++)
#pragma unroll
        for (int c = 0; c < 4; c++) o[dj][c] = 0.f;
    float m_a = -1e30f, m_b = -1e30f, l_a = 0.f, l_b = 0.f;

    const int rA = m0 + wm + gid;
    const int rB = rA + 8;
    const int ntiles = m0 / FBN + FBM / FBN;  // m0/64 + 2

#pragma unroll 1
    for (int t = 0; t < ntiles; t++) {
        const int buf = t & 1;
        const uint32_t* Ks = Ksb + buf * KTILE;
        const uint32_t* Vt = Vtb + buf * VTILE;
        const int* mk = mkb + buf * FBN;
        const int n0 = t * FBN;
        const bool more = (t + 1 < ntiles);

        // ---- stage next KV tile in registers ----
        float4 ka[8], va[8];
        int mreg = 1;
        if (more) {
            const int nn = n0 + FBN;
#pragma unroll
            for (int i = 0; i < 8; i++) {
                int f = tid + i * 256;
                int row = f >> 5, c4 = (f & 31) * 4;
                ka[i] = *(const float4*)(K + (size_t)(b * LSEQ + nn + row) * HD + c4);
            }
#pragma unroll
            for (int i = 0; i < 8; i++) {
                int f = tid + i * 256;
                int row = f & 63, c4 = (f >> 6) * 4;
                va[i] = *(const float4*)(V + (size_t)(b * LSEQ + nn + row) * HD + c4);
            }
            if (tid < FBN) mreg = mask[b * LSEQ + nn + tid];
        }

        if (n0 <= m0 + wm + 15) {   // per-warp causal skip
            // ---- S = Q K^T : warp m16 x n64, 8 x k16 ----
            float s[8][4];
#pragma unroll
            for (int j = 0; j < 8; j++)
#pragma unroll
                for (int c = 0; c < 4; c++) s[j][c] = 0.f;
#pragma unroll
            for (int kk = 0; kk < 8; kk++) {
                const int kw = kk * 8;
                uint32_t a[4];
                a[0] = Qs[(wm + gid) * QSTR + kw + tig];
                a[1] = Qs[(wm + gid + 8) * QSTR + kw + tig];
                a[2] = Qs[(wm + gid) * QSTR + kw + tig + 4];
                a[3] = Qs[(wm + gid + 8) * QSTR + kw + tig + 4];
#pragma unroll
                for (int j = 0; j < 8; j++) {
                    uint32_t b0 = Ks[(j * 8 + gid) * QSTR + kw + tig];
                    uint32_t b1 = Ks[(j * 8 + gid) * QSTR + kw + tig + 4];
                    mma_f16(s[j], a, b0, b1);
                }
            }

            // ---- scale + causal + pad mask; warp-local row max ----
            float mxA = -1e30f, mxB = -1e30f;
#pragma unroll
            for (int j = 0; j < 8; j++) {
#pragma unroll
                for (int c = 0; c < 4; c++) {
                    int lcol = j * 8 + 2 * tig + (c & 1);
                    int col = n0 + lcol;
                    int r = (c < 2) ? rA : rB;
                    float v = s[j][c] * SCALE;
                    if (col > r || mk[lcol] == 0) v = -1e30f;
                    s[j][c] = v;
                    if (c < 2) mxA = fmaxf(mxA, v); else mxB = fmaxf(mxB, v);
                }
            }
            mxA = fmaxf(mxA, __shfl_xor_sync(0xffffffffu, mxA, 1));
            mxA = fmaxf(mxA, __shfl_xor_sync(0xffffffffu, mxA, 2));
            mxB = fmaxf(mxB, __shfl_xor_sync(0xffffffffu, mxB, 1));
            mxB = fmaxf(mxB, __shfl_xor_sync(0xffffffffu, mxB, 2));
            const float mnA = fmaxf(m_a, mxA), mnB = fmaxf(m_b, mxB);
            const float crA = __expf(m_a - mnA), crB = __expf(m_b - mnB);
            m_a = mnA; m_b = mnB;

            // ---- exp + row sums ----
            float smA = 0.f, smB = 0.f;
#pragma unroll
            for (int j = 0; j < 8; j++) {
#pragma unroll
                for (int c = 0; c < 4; c++) {
                    float p = __expf(s[j][c] - ((c < 2) ? mnA : mnB));
                    s[j][c] = p;
                    if (c < 2) smA += p; else smB += p;
                }
            }
            smA += __shfl_xor_sync(0xffffffffu, smA, 1);
            smA += __shfl_xor_sync(0xffffffffu, smA, 2);
            smB += __shfl_xor_sync(0xffffffffu, smB, 1);
            smB += __shfl_xor_sync(0xffffffffu, smB, 2);
            l_a = l_a * crA + smA;
            l_b = l_b * crB + smB;

            // ---- rescale O, then O += P V (P packs straight into A-fragments) ----
#pragma unroll
            for (int dj = 0; dj < 16; dj++) {
                o[dj][0] *= crA; o[dj][1] *= crA;
                o[dj][2] *= crB; o[dj][3] *= crB;
            }
#pragma unroll
            for (int kk = 0; kk < 4; kk++) {   // k16 over 64 keys
                uint32_t a[4];
                a[0] = f16x2(s[2 * kk][0],     s[2 * kk][1]);      // row gid,   k-lo
                a[1] = f16x2(s[2 * kk][2],     s[2 * kk][3]);      // row gid+8, k-lo
                a[2] = f16x2(s[2 * kk + 1][0], s[2 * kk + 1][1]);  // row gid,   k-hi
                a[3] = f16x2(s[2 * kk + 1][2], s[2 * kk + 1][3]);  // row gid+8, k-hi
                const int kw = kk * 8;
#pragma unroll
                for (int dj = 0; dj < 16; dj++) {
                    uint32_t b0 = Vt[(dj * 8 + gid) * VSTR + kw + tig];
                    uint32_t b1 = Vt[(dj * 8 + gid) * VSTR + kw + tig + 4];
                    mma_f16(o[dj], a, b0, b1);
                }
            }
        }

        // ---- commit staged tile into other buffer ----
        if (more) {
            uint32_t* Kd = Ksb + (buf ^ 1) * KTILE;
            __half* hV = (__half*)(Vtb + (buf ^ 1) * VTILE);
#pragma unroll
            for (int i = 0; i < 8; i++) {
                int f = tid + i * 256;
                int row = f >> 5;
                *(uint2*)&Kd[row * QSTR + (f & 31) * 2] =
                    make_uint2(f16x2(ka[i].x, ka[i].y), f16x2(ka[i].z, ka[i].w));
            }
#pragma unroll
            for (int i = 0; i < 8; i++) {
                int f = tid + i * 256;
                int row = f & 63, c4 = (f >> 6) * 4;
                int base = (row >> 1) * 2 + (row & 1);
                hV[(c4 + 0) * (VSTR * 2) + base] = __float2half_rn(va[i].x);
                hV[(c4 + 1) * (VSTR * 2) + base] = __float2half_rn(va[i].y);
                hV[(c4 + 2) * (VSTR * 2) + base] = __float2half_rn(va[i].z);
                hV[(c4 + 3) * (VSTR * 2) + base] = __float2half_rn(va[i].w);
            }
            if (tid < FBN) mkb[(buf ^ 1) * FBN + tid] = mreg;
        }
        __syncthreads();
    }

    // ---- normalize + write ----
    const float invA = (l_a > 0.f) ? (1.f / l_a) : 0.f;
    const float invB = (l_b > 0.f) ? (1.f / l_b) : 0.f;
    float* rowA = O + (size_t)(b * LSEQ + m0 + wm + gid) * HID + h * HD;
    float* rowB = rowA + (size_t)8 * HID;
#pragma unroll
    for (int dj = 0; dj < 16; dj++) {
        int cb = dj * 8 + 2 * tig;
        *(float2*)(rowA + cb) = make_float2(o[dj][0] * invA, o[dj][1] * invA);
        *(float2*)(rowB + cb) = make_float2(o[dj][2] * invB, o[dj][3] * invB);
    }
}

// ---------------- launch ----------------
extern "C" void kernel_launch(void* const* d_in, const int* in_sizes, int n_in,
                              void* d_out, int out_size)
{
    const float* x   = (const float*)d_in[0];
    const int* mask  = (const int*)d_in[1];
    const float* Wq  = (const float*)d_in[2];
    const float* Wk  = (const float*)d_in[3];
    const float* Wv  = (const float*)d_in[4];
    const float* Wo  = (const float*)d_in[5];
    float* out       = (float*)d_out;

    float *Qp, *Kp, *Vp, *Op;
    cudaGetSymbolAddress((void**)&Qp, g_Q);
    cudaGetSymbolAddress((void**)&Kp, g_K);
    cudaGetSymbolAddress((void**)&Vp, g_V);
    cudaGetSymbolAddress((void**)&Op, g_O);

    cudaFuncSetAttribute(gemm_tc, cudaFuncAttributeMaxDynamicSharedMemorySize, GEMM_SMEM);
    cudaFuncSetAttribute(flash_tc, cudaFuncAttributeMaxDynamicSharedMemorySize, FLASH_SMEM);

    gemm_tc<<<dim3(HID / TBN, MTOT / TBM), 256, GEMM_SMEM>>>(x, Wq, Qp, HID);
    gemm_tc<<<dim3(HD / TBN, MTOT / TBM), 256, GEMM_SMEM>>>(x, Wk, Kp, HD);
    gemm_tc<<<dim3(HD / TBN, MTOT / TBM), 256, GEMM_SMEM>>>(x, Wv, Vp, HD);
    flash_tc<<<dim3(LSEQ / FBM, BSZ * NH), 256, FLASH_SMEM>>>(Qp, Kp, Vp, mask, Op);
    gemm_tc<<<dim3(HID / TBN, MTOT / TBM), 256, GEMM_SMEM>>>(Op, Wo, out, HID);
}

// round 16
// speedup vs baseline: 2.0670x; 1.3041x over previous
#include <cuda_runtime.h>
#include <cuda_fp16.h>
#include <cstdint>
#include <math.h>

// Problem constants
#define BSZ 2
#define LSEQ 2048
#define HID 2048
#define NH 16
#define HD 128
#define MTOT (BSZ * LSEQ)          // 4096
#define SCALE 0.08838834764831845f // 1/sqrt(128)

// ---------------- scratch (no allocations allowed) ----------------
__device__ float g_Q[MTOT * HID];  // 32 MB
__device__ float g_K[MTOT * HD];   // 2 MB
__device__ float g_V[MTOT * HD];   // 2 MB
__device__ float g_O[MTOT * HID];  // 32 MB

__device__ __forceinline__ uint32_t f16x2(float lo, float hi) {
    __half2 h = __floats2half2_rn(lo, hi);
    return *reinterpret_cast<uint32_t*>(&h);
}

// D(f32) += A(f16) * B(f16): m16n8k16
__device__ __forceinline__ void mma_f16(float* c, const uint32_t* a,
                                        uint32_t b0, uint32_t b1) {
    asm volatile(
        "mma.sync.aligned.m16n8k16.row.col.f32.f16.f16.f32 "
        "{%0,%1,%2,%3}, {%4,%5,%6,%7}, {%8,%9}, {%0,%1,%2,%3};\n"
        : "+f"(c[0]), "+f"(c[1]), "+f"(c[2]), "+f"(c[3])
        : "r"(a[0]), "r"(a[1]), "r"(a[2]), "r"(a[3]), "r"(b0), "r"(b1));
}

__device__ __forceinline__ void ldsm_x4(uint32_t& r0, uint32_t& r1,
                                        uint32_t& r2, uint32_t& r3, uint32_t saddr) {
    asm volatile("ldmatrix.sync.aligned.m8n8.x4.shared.b16 {%0,%1,%2,%3}, [%4];"
                 : "=r"(r0), "=r"(r1), "=r"(r2), "=r"(r3) : "r"(saddr));
}

// ================= fp16 mma GEMM: C[M,N] = A[M,K] @ W[N,K]^T =================
// CTA 128x128, 256 threads (8 warps as 4x2; warp tile 32x64). K chunk 32 (2 k16).
// Fragment loads via ldmatrix.x4. Row stride 20 words = 80B (16B multiple; 8-row
// phases mod 128 distinct -> conflict-free LDSM).
#define TBM 128
#define TBN 128
#define TBK 32
#define GK 2048
#define NCHUNK (GK / TBK)   // 64
#define APAD 20             // words per row (16 data + 4 pad)
#define ATILE (TBM * APAD)  // words per A (or B) tile
#define STAGEF (2 * ATILE)
#define GEMM_SMEM (2 * STAGEF * (int)sizeof(uint32_t))  // 40960 B

__global__ __launch_bounds__(256) void gemm_tc(
    const float* __restrict__ A, const float* __restrict__ W,
    float* __restrict__ C, int ldc)
{
    extern __shared__ uint32_t smw[];
    const int tid = threadIdx.x;
    const int lane = tid & 31;
    const int wid = tid >> 5;
    const int warp_m = (wid & 3) * 32;
    const int warp_n = (wid >> 2) * 64;
    const int gid = lane >> 2;
    const int tig = lane & 3;
    const int bm = blockIdx.y * TBM;
    const int bn = blockIdx.x * TBN;

    const int lrow = tid >> 3;           // 0..31 (+32*i)
    const int lc4 = (tid & 7) * 4;       // f32 col
    const int wcol = (tid & 7) * 2;      // smem word col

    const uint32_t smem0 = (uint32_t)__cvta_generic_to_shared(smw);
    // ldmatrix lane offsets (bytes). A-pattern: bit3->row+8, bit4->k+16B.
    uint32_t aoff[2];
#pragma unroll
    for (int i = 0; i < 2; i++) {
        int row = warp_m + i * 16 + (lane & 7) + ((lane & 8) ? 8 : 0);
        aoff[i] = (uint32_t)((row * APAD + ((lane >> 4) & 1) * 4) * 4);
    }
    // B-pattern: bit4->row+8 (next n8), bit3->k+16B.
    uint32_t boff[4];
#pragma unroll
    for (int jp = 0; jp < 4; jp++) {
        int row = warp_n + jp * 16 + (lane & 7) + ((lane >> 4) & 1) * 8;
        boff[jp] = (uint32_t)((row * APAD + ((lane >> 3) & 1) * 4) * 4);
    }

    float acc[2][8][4];
#pragma unroll
    for (int i = 0; i < 2; i++)
#pragma unroll
        for (int j = 0; j < 8; j++)
#pragma unroll
            for (int q = 0; q < 4; q++) acc[i][j][q] = 0.f;

    float4 ra[4], rb[4];

    // ---- prefetch chunk 0 ----
#pragma unroll
    for (int i = 0; i < 4; i++) {
        int row = lrow + i * 32;
        ra[i] = *(const float4*)(A + (size_t)(bm + row) * GK + lc4);
        rb[i] = *(const float4*)(W + (size_t)(bn + row) * GK + lc4);
    }
#pragma unroll
    for (int i = 0; i < 4; i++) {
        int row = lrow + i * 32;
        *(uint2*)&smw[row * APAD + wcol] =
            make_uint2(f16x2(ra[i].x, ra[i].y), f16x2(ra[i].z, ra[i].w));
        *(uint2*)&smw[ATILE + row * APAD + wcol] =
            make_uint2(f16x2(rb[i].x, rb[i].y), f16x2(rb[i].z, rb[i].w));
    }
    __syncthreads();

#pragma unroll 1
    for (int c = 0; c < NCHUNK; c++) {
        const int s = c & 1;
        const bool more = (c + 1 < NCHUNK);
        if (more) {
            const int k0 = (c + 1) * TBK;
#pragma unroll
            for (int i = 0; i < 4; i++) {
                int row = lrow + i * 32;
                ra[i] = *(const float4*)(A + (size_t)(bm + row) * GK + k0 + lc4);
                rb[i] = *(const float4*)(W + (size_t)(bn + row) * GK + k0 + lc4);
            }
        }

        const uint32_t abase = smem0 + (uint32_t)(s * STAGEF) * 4;
        const uint32_t bbase = abase + (uint32_t)ATILE * 4;
#pragma unroll
        for (int ks = 0; ks < 2; ks++) {            // 2 x k16
            const uint32_t kB = (uint32_t)(ks * 8) * 4;
            uint32_t af[2][4];
            ldsm_x4(af[0][0], af[0][1], af[0][2], af[0][3], abase + kB + aoff[0]);
            ldsm_x4(af[1][0], af[1][1], af[1][2], af[1][3], abase + kB + aoff[1]);
#pragma unroll
            for (int jp = 0; jp < 4; jp++) {
                uint32_t b0, b1, b2, b3;
                ldsm_x4(b0, b1, b2, b3, bbase + kB + boff[jp]);
                mma_f16(acc[0][2 * jp],     af[0], b0, b1);
                mma_f16(acc[1][2 * jp],     af[1], b0, b1);
                mma_f16(acc[0][2 * jp + 1], af[0], b2, b3);
                mma_f16(acc[1][2 * jp + 1], af[1], b2, b3);
            }
        }

        if (more) {
            uint32_t* Ad = &smw[(s ^ 1) * STAGEF];
            uint32_t* Bd = &smw[(s ^ 1) * STAGEF + ATILE];
#pragma unroll
            for (int i = 0; i < 4; i++) {
                int row = lrow + i * 32;
                *(uint2*)&Ad[row * APAD + wcol] =
                    make_uint2(f16x2(ra[i].x, ra[i].y), f16x2(ra[i].z, ra[i].w));
                *(uint2*)&Bd[row * APAD + wcol] =
                    make_uint2(f16x2(rb[i].x, rb[i].y), f16x2(rb[i].z, rb[i].w));
            }
        }
        __syncthreads();
    }

    // ---- epilogue ----
#pragma unroll
    for (int i = 0; i < 2; i++) {
        int r0 = bm + warp_m + i * 16 + gid;
#pragma unroll
        for (int j = 0; j < 8; j++) {
            int cn = bn + warp_n + j * 8 + 2 * tig;
            *(float2*)(C + (size_t)r0 * ldc + cn) =
                make_float2(acc[i][j][0], acc[i][j][1]);
            *(float2*)(C + (size_t)(r0 + 8) * ldc + cn) =
                make_float2(acc[i][j][2], acc[i][j][3]);
        }
    }
}

// ============== Flash attention v5 (fp16 mma + ldmatrix, causal, MQA) ==============
// Same structure as v4 (round-13 WIN); all fragment loads via ldmatrix.x4.
#define FBM 128
#define FBN 64
#define QSTR 68    // words/row (64 data + 4 pad); 272B stride, 16B-aligned
#define VSTR 36    // words/row (32 data + 4 pad); 144B stride
#define KTILE (FBN * QSTR)   // 4352 words
#define VTILE (HD * VSTR)    // 4608 words
#define FL_QS 0
#define FL_KS (FL_QS + FBM * QSTR)      // Qs: 8704 words
#define FL_VT (FL_KS + 2 * KTILE)       // Ks: 2 x 4352
#define FL_MK (FL_VT + 2 * VTILE)       // Vt: 2 x 4608
#define FLASH_SMEM ((FL_MK + 2 * FBN) * (int)sizeof(uint32_t))  // 107,520 B

__global__ __launch_bounds__(256) void flash_tc(
    const float* __restrict__ Q, const float* __restrict__ K,
    const float* __restrict__ V, const int* __restrict__ mask,
    float* __restrict__ O)
{
    extern __shared__ uint32_t fsw[];
    uint32_t* Qs = fsw + FL_QS;
    uint32_t* Ksb = fsw + FL_KS;
    uint32_t* Vtb = fsw + FL_VT;
    int* mkb = (int*)(fsw + FL_MK);

    const int m0 = (gridDim.x - 1 - blockIdx.x) * FBM;  // heavy tiles first
    const int bh = blockIdx.y;
    const int b = bh / NH;
    const int h = bh % NH;
    const int tid = threadIdx.x;
    const int lane = tid & 31;
    const int wid = tid >> 5;
    const int gid = lane >> 2;
    const int tig = lane & 3;
    const int wm = wid * 16;

    const uint32_t smem0 = (uint32_t)__cvta_generic_to_shared(fsw);
    // Q A-fragment ldmatrix offset (bytes): bit3->row+8, bit4->k+16B
    const uint32_t qoff = smem0 + (uint32_t)(((wm + (lane & 7) + ((lane & 8) ? 8 : 0)) * QSTR
                                   + ((lane >> 4) & 1) * 4) * 4);
    // K B-fragment: bit4->row+8 (next n8), bit3->k+16B; jp covers 2 n8 tiles
    uint32_t koff[4];
#pragma unroll
    for (int jp = 0; jp < 4; jp++) {
        int row = jp * 16 + (lane & 7) + ((lane >> 4) & 1) * 8;
        koff[jp] = (uint32_t)((row * QSTR + ((lane >> 3) & 1) * 4) * 4) + (uint32_t)(FL_KS * 4) + smem0;
    }
    // V B-fragment: rows are d; same B pattern; djp covers 2 d8 tiles
    uint32_t voff[8];
#pragma unroll
    for (int djp = 0; djp < 8; djp++) {
        int row = djp * 16 + (lane & 7) + ((lane >> 4) & 1) * 8;
        voff[djp] = (uint32_t)((row * VSTR + ((lane >> 3) & 1) * 4) * 4) + (uint32_t)(FL_VT * 4) + smem0;
    }

    // ---- Q tile (128 x 128) -> fp16 smem ----
    for (int f = tid; f < FBM * 32; f += 256) {
        int row = f >> 5, c4 = (f & 31) * 4;
        float4 v = *(const float4*)(Q + (size_t)(b * LSEQ + m0 + row) * HID + h * HD + c4);
        *(uint2*)&Qs[row * QSTR + (f & 31) * 2] =
            make_uint2(f16x2(v.x, v.y), f16x2(v.z, v.w));
    }
    // ---- prologue: KV tile 0 into buffer 0 ----
    for (int f = tid; f < FBN * 32; f += 256) {
        int row = f >> 5;
        float4 v = *(const float4*)(K + (size_t)(b * LSEQ + row) * HD + (f & 31) * 4);
        *(uint2*)&Ksb[row * QSTR + (f & 31) * 2] =
            make_uint2(f16x2(v.x, v.y), f16x2(v.z, v.w));
    }
    {
        __half* hV = (__half*)Vtb;
        for (int f = tid; f < FBN * 32; f += 256) {
            int row = f & 63, c4 = (f >> 6) * 4;
            float4 v = *(const float4*)(V + (size_t)(b * LSEQ + row) * HD + c4);
            hV[(c4 + 0) * (VSTR * 2) + row] = __float2half_rn(v.x);
            hV[(c4 + 1) * (VSTR * 2) + row] = __float2half_rn(v.y);
            hV[(c4 + 2) * (VSTR * 2) + row] = __float2half_rn(v.z);
            hV[(c4 + 3) * (VSTR * 2) + row] = __float2half_rn(v.w);
        }
    }
    if (tid < FBN) mkb[tid] = mask[b * LSEQ + tid];
    __syncthreads();

    float o[16][4];
#pragma unroll
    for (int dj = 0; dj < 16; dj++)
#pragma unroll
        for (int c = 0; c < 4; c++) o[dj][c] = 0.f;
    float m_a = -1e30f, m_b = -1e30f, l_a = 0.f, l_b = 0.f;

    const int rA = m0 + wm + gid;
    const int rB = rA + 8;
    const int ntiles = m0 / FBN + FBM / FBN;  // m0/64 + 2

#pragma unroll 1
    for (int t = 0; t < ntiles; t++) {
        const int buf = t & 1;
        const uint32_t kbufB = (uint32_t)(buf * KTILE) * 4;
        const uint32_t vbufB = (uint32_t)(buf * VTILE) * 4;
        const int* mk = mkb + buf * FBN;
        const int n0 = t * FBN;
        const bool more = (t + 1 < ntiles);

        // ---- stage next KV tile in registers ----
        float4 ka[8], va[8];
        int mreg = 1;
        if (more) {
            const int nn = n0 + FBN;
#pragma unroll
            for (int i = 0; i < 8; i++) {
                int f = tid + i * 256;
                int row = f >> 5;
                ka[i] = *(const float4*)(K + (size_t)(b * LSEQ + nn + row) * HD + (f & 31) * 4);
            }
#pragma unroll
            for (int i = 0; i < 8; i++) {
                int f = tid + i * 256;
                int row = f & 63, c4 = (f >> 6) * 4;
                va[i] = *(const float4*)(V + (size_t)(b * LSEQ + nn + row) * HD + c4);
            }
            if (tid < FBN) mreg = mask[b * LSEQ + nn + tid];
        }

        if (n0 <= m0 + wm + 15) {   // per-warp causal skip
            // ---- S = Q K^T : warp m16 x n64, 8 x k16, ldmatrix fragments ----
            float s[8][4];
#pragma unroll
            for (int j = 0; j < 8; j++)
#pragma unroll
                for (int c = 0; c < 4; c++) s[j][c] = 0.f;
#pragma unroll
            for (int kk = 0; kk < 8; kk++) {
                const uint32_t kB = (uint32_t)kk * 32;
                uint32_t a[4];
                ldsm_x4(a[0], a[1], a[2], a[3], qoff + kB);
#pragma unroll
                for (int jp = 0; jp < 4; jp++) {
                    uint32_t b0, b1, b2, b3;
                    ldsm_x4(b0, b1, b2, b3, koff[jp] + kbufB + kB);
                    mma_f16(s[2 * jp],     a, b0, b1);
                    mma_f16(s[2 * jp + 1], a, b2, b3);
                }
            }

            // ---- scale + causal + pad mask; warp-local row max ----
            float mxA = -1e30f, mxB = -1e30f;
#pragma unroll
            for (int j = 0; j < 8; j++) {
#pragma unroll
                for (int c = 0; c < 4; c++) {
                    int lcol = j * 8 + 2 * tig + (c & 1);
                    int col = n0 + lcol;
                    int r = (c < 2) ? rA : rB;
                    float v = s[j][c] * SCALE;
                    if (col > r || mk[lcol] == 0) v = -1e30f;
                    s[j][c] = v;
                    if (c < 2) mxA = fmaxf(mxA, v); else mxB = fmaxf(mxB, v);
                }
            }
            mxA = fmaxf(mxA, __shfl_xor_sync(0xffffffffu, mxA, 1));
            mxA = fmaxf(mxA, __shfl_xor_sync(0xffffffffu, mxA, 2));
            mxB = fmaxf(mxB, __shfl_xor_sync(0xffffffffu, mxB, 1));
            mxB = fmaxf(mxB, __shfl_xor_sync(0xffffffffu, mxB, 2));
            const float mnA = fmaxf(m_a, mxA), mnB = fmaxf(m_b, mxB);
            const float crA = __expf(m_a - mnA), crB = __expf(m_b - mnB);
            m_a = mnA; m_b = mnB;

            // ---- exp + row sums ----
            float smA = 0.f, smB = 0.f;
#pragma unroll
            for (int j = 0; j < 8; j++) {
#pragma unroll
                for (int c = 0; c < 4; c++) {
                    float p = __expf(s[j][c] - ((c < 2) ? mnA : mnB));
                    s[j][c] = p;
                    if (c < 2) smA += p; else smB += p;
                }
            }
            smA += __shfl_xor_sync(0xffffffffu, smA, 1);
            smA += __shfl_xor_sync(0xffffffffu, smA, 2);
            smB += __shfl_xor_sync(0xffffffffu, smB, 1);
            smB += __shfl_xor_sync(0xffffffffu, smB, 2);
            l_a = l_a * crA + smA;
            l_b = l_b * crB + smB;

            // ---- rescale O, then O += P V (P packs straight into A-fragments) ----
#pragma unroll
            for (int dj = 0; dj < 16; dj++) {
                o[dj][0] *= crA; o[dj][1] *= crA;
                o[dj][2] *= crB; o[dj][3] *= crB;
            }
#pragma unroll
            for (int kk = 0; kk < 4; kk++) {   // k16 over 64 keys
                uint32_t a[4];
                a[0] = f16x2(s[2 * kk][0],     s[2 * kk][1]);
                a[1] = f16x2(s[2 * kk][2],     s[2 * kk][3]);
                a[2] = f16x2(s[2 * kk + 1][0], s[2 * kk + 1][1]);
                a[3] = f16x2(s[2 * kk + 1][2], s[2 * kk + 1][3]);
                const uint32_t kB = (uint32_t)kk * 32;
#pragma unroll
                for (int djp = 0; djp < 8; djp++) {
                    uint32_t b0, b1, b2, b3;
                    ldsm_x4(b0, b1, b2, b3, voff[djp] + vbufB + kB);
                    mma_f16(o[2 * djp],     a, b0, b1);
                    mma_f16(o[2 * djp + 1], a, b2, b3);
                }
            }
        }

        // ---- commit staged tile into other buffer ----
        if (more) {
            uint32_t* Kd = Ksb + (buf ^ 1) * KTILE;
            __half* hV = (__half*)(Vtb + (buf ^ 1) * VTILE);
#pragma unroll
            for (int i = 0; i < 8; i++) {
                int f = tid + i * 256;
                int row = f >> 5;
                *(uint2*)&Kd[row * QSTR + (f & 31) * 2] =
                    make_uint2(f16x2(ka[i].x, ka[i].y), f16x2(ka[i].z, ka[i].w));
            }
#pragma unroll
            for (int i = 0; i < 8; i++) {
                int f = tid + i * 256;
                int row = f & 63, c4 = (f >> 6) * 4;
                hV[(c4 + 0) * (VSTR * 2) + row] = __float2half_rn(va[i].x);
                hV[(c4 + 1) * (VSTR * 2) + row] = __float2half_rn(va[i].y);
                hV[(c4 + 2) * (VSTR * 2) + row] = __float2half_rn(va[i].z);
                hV[(c4 + 3) * (VSTR * 2) + row] = __float2half_rn(va[i].w);
            }
            if (tid < FBN) mkb[(buf ^ 1) * FBN + tid] = mreg;
        }
        __syncthreads();
    }

    // ---- normalize + write ----
    const float invA = (l_a > 0.f) ? (1.f / l_a) : 0.f;
    const float invB = (l_b > 0.f) ? (1.f / l_b) : 0.f;
    float* rowA = O + (size_t)(b * LSEQ + m0 + wm + gid) * HID + h * HD;
    float* rowB = rowA + (size_t)8 * HID;
#pragma unroll
    for (int dj = 0; dj < 16; dj++) {
        int cb = dj * 8 + 2 * tig;
        *(float2*)(rowA + cb) = make_float2(o[dj][0] * invA, o[dj][1] * invA);
        *(float2*)(rowB + cb) = make_float2(o[dj][2] * invB, o[dj][3] * invB);
    }
}

// ---------------- launch ----------------
extern "C" void kernel_launch(void* const* d_in, const int* in_sizes, int n_in,
                              void* d_out, int out_size)
{
    const float* x   = (const float*)d_in[0];
    const int* mask  = (const int*)d_in[1];
    const float* Wq  = (const float*)d_in[2];
    const float* Wk  = (const float*)d_in[3];
    const float* Wv  = (const float*)d_in[4];
    const float* Wo  = (const float*)d_in[5];
    float* out       = (float*)d_out;

    float *Qp, *Kp, *Vp, *Op;
    cudaGetSymbolAddress((void**)&Qp, g_Q);
    cudaGetSymbolAddress((void**)&Kp, g_K);
    cudaGetSymbolAddress((void**)&Vp, g_V);
    cudaGetSymbolAddress((void**)&Op, g_O);

    cudaFuncSetAttribute(gemm_tc, cudaFuncAttributeMaxDynamicSharedMemorySize, GEMM_SMEM);
    cudaFuncSetAttribute(flash_tc, cudaFuncAttributeMaxDynamicSharedMemorySize, FLASH_SMEM);

    gemm_tc<<<dim3(HID / TBN, MTOT / TBM), 256, GEMM_SMEM>>>(x, Wq, Qp, HID);
    gemm_tc<<<dim3(HD / TBN, MTOT / TBM), 256, GEMM_SMEM>>>(x, Wk, Kp, HD);
    gemm_tc<<<dim3(HD / TBN, MTOT / TBM), 256, GEMM_SMEM>>>(x, Wv, Vp, HD);
    flash_tc<<<dim3(LSEQ / FBM, BSZ * NH), 256, FLASH_SMEM>>>(Qp, Kp, Vp, mask, Op);
    gemm_tc<<<dim3(HID / TBN, MTOT / TBM), 256, GEMM_SMEM>>>(Op, Wo, out, HID);
}